// round 13
// baseline (speedup 1.0000x reference)
#include <cuda_runtime.h>
#include <cuda_bf16.h>
#include <cuda_fp16.h>
#include <math.h>
#include <stdint.h>

// ---------------- problem constants ----------------
#define NN   50000   // nodes
#define EE   400000  // edges per relation
#define RR   3       // relations
#define FIN  128     // input features
#define FHID 64      // hidden features
#define FC   40      // classes
#define NH   3       // heads
#define NEG_SLOPE 0.2f

#define SCRATCH_BYTES (192ull * 1024 * 1024)
__device__ __align__(256) unsigned char g_scratch[SCRATCH_BYTES];

__device__ __forceinline__ float lrelu(float x) { return x > 0.f ? x : NEG_SLOPE * x; }

// order-preserving float<->int transform (involution) for atomicMax on float
__device__ __forceinline__ int encf(float f) {
    int i = __float_as_int(f);
    return i < 0 ? (i ^ 0x7fffffff) : i;
}
__device__ __forceinline__ float decf(int i) {
    return __int_as_float(i < 0 ? (i ^ 0x7fffffff) : i);
}

// ---------------- CSR build ----------------
__global__ void count_k(const int* __restrict__ dst, int* __restrict__ cnt) {
    int i = blockIdx.x * blockDim.x + threadIdx.x;
    if (i >= RR * EE) return;
    int r = i / EE;
    atomicAdd(&cnt[r * NN + dst[i]], 1);
}

__global__ void scan_k(const int* __restrict__ cnt, int* __restrict__ ptr, int* __restrict__ cur) {
    const int r = blockIdx.x;
    const int t = threadIdx.x;
    const int CH = (NN + 1023) / 1024;
    int s0 = t * CH;
    int s1 = s0 + CH; if (s1 > NN) s1 = NN;
    if (s0 > NN) s0 = NN;
    int sum = 0;
    for (int n = s0; n < s1; n++) sum += cnt[r * NN + n];
    __shared__ int sh[1024];
    sh[t] = sum;
    __syncthreads();
    for (int off = 1; off < 1024; off <<= 1) {
        int v = (t >= off) ? sh[t - off] : 0;
        __syncthreads();
        sh[t] += v;
        __syncthreads();
    }
    int base = sh[t] - sum;
    for (int n = s0; n < s1; n++) {
        ptr[r * (NN + 1) + n] = base;
        cur[r * NN + n] = base;
        base += cnt[r * NN + n];
    }
    if (t == 1023) ptr[r * (NN + 1) + NN] = sh[1023];
}

__global__ void scatter_k(const int* __restrict__ src, const int* __restrict__ dst,
                          int* __restrict__ cur, int* __restrict__ csrc) {
    int i = blockIdx.x * blockDim.x + threadIdx.x;
    if (i >= RR * EE) return;
    int r = i / EE;
    int d = dst[i];
    int pos = atomicAdd(&cur[r * NN + d], 1);
    csrc[(size_t)r * EE + pos] = src[i];
}

// ---------------- fp32 -> (fp16 hi, fp16 lo) split, one pass ----------------
__global__ void split16_k(const float* __restrict__ in, __half* __restrict__ hi,
                          __half* __restrict__ lo, int n4) {
    int i = blockIdx.x * blockDim.x + threadIdx.x;
    if (i >= n4) return;
    float4 v = ((const float4*)in)[i];
    __half h0 = __float2half(v.x), h1 = __float2half(v.y);
    __half h2 = __float2half(v.z), h3 = __float2half(v.w);
    __half hv[4] = {h0, h1, h2, h3};
    __half lv[4] = {
        __float2half(v.x - __half2float(h0)),
        __float2half(v.y - __half2float(h1)),
        __float2half(v.z - __half2float(h2)),
        __float2half(v.w - __half2float(h3))};
    ((uint2*)hi)[i] = *(uint2*)hv;
    ((uint2*)lo)[i] = *(uint2*)lv;
}

// ---------------- gmax init + global el max per (rel,head) ----------------
__global__ void initgmax_k(int* g) {
    if (threadIdx.x < 2 * RR * 4) g[threadIdx.x] = encf(-1e30f);
}

__global__ void maxel_k(const float4* __restrict__ el, int* __restrict__ gmax) {
    const int r = blockIdx.y;
    const int n = blockIdx.x * blockDim.x + threadIdx.x;
    float m0 = -1e30f, m1 = -1e30f, m2 = -1e30f;
    if (n < NN) {
        float4 e = el[(size_t)r * NN + n];
        m0 = e.x; m1 = e.y; m2 = e.z;
    }
#pragma unroll
    for (int o = 16; o; o >>= 1) {
        m0 = fmaxf(m0, __shfl_xor_sync(0xffffffffu, m0, o));
        m1 = fmaxf(m1, __shfl_xor_sync(0xffffffffu, m1, o));
        m2 = fmaxf(m2, __shfl_xor_sync(0xffffffffu, m2, o));
    }
    __shared__ float s0[8], s1[8], s2[8];
    const int warp = threadIdx.x >> 5, lane = threadIdx.x & 31;
    if (lane == 0) { s0[warp] = m0; s1[warp] = m1; s2[warp] = m2; }
    __syncthreads();
    if (warp == 0) {
        m0 = (lane < 8) ? s0[lane] : -1e30f;
        m1 = (lane < 8) ? s1[lane] : -1e30f;
        m2 = (lane < 8) ? s2[lane] : -1e30f;
#pragma unroll
        for (int o = 4; o; o >>= 1) {
            m0 = fmaxf(m0, __shfl_xor_sync(0xffffffffu, m0, o));
            m1 = fmaxf(m1, __shfl_xor_sync(0xffffffffu, m1, o));
            m2 = fmaxf(m2, __shfl_xor_sync(0xffffffffu, m2, o));
        }
        if (lane == 0) {
            atomicMax(&gmax[r * 4 + 0], encf(m0));
            atomicMax(&gmax[r * 4 + 1], encf(m1));
            atomicMax(&gmax[r * 4 + 2], encf(m2));
        }
    }
}

// ---------------- mma / ldmatrix helpers ----------------
__device__ __forceinline__ void mma16816h(float* c, const uint32_t* a, uint32_t b0, uint32_t b1) {
    asm volatile(
        "mma.sync.aligned.m16n8k16.row.col.f32.f16.f16.f32 "
        "{%0,%1,%2,%3}, {%4,%5,%6,%7}, {%8,%9}, {%0,%1,%2,%3};"
        : "+f"(c[0]), "+f"(c[1]), "+f"(c[2]), "+f"(c[3])
        : "r"(a[0]), "r"(a[1]), "r"(a[2]), "r"(a[3]), "r"(b0), "r"(b1));
}

__device__ __forceinline__ void ldsm4(uint32_t* r, uint32_t addr) {
    asm volatile("ldmatrix.sync.aligned.m8n8.x4.shared.b16 {%0,%1,%2,%3}, [%4];"
                 : "=r"(r[0]), "=r"(r[1]), "=r"(r[2]), "=r"(r[3]) : "r"(addr));
}
__device__ __forceinline__ void ldsm2(uint32_t* r, uint32_t addr) {
    asm volatile("ldmatrix.sync.aligned.m8n8.x2.shared.b16 {%0,%1}, [%2];"
                 : "=r"(r[0]), "=r"(r[1]) : "r"(addr));
}
__device__ __forceinline__ uint32_t smem_u32(const void* p) {
    return (uint32_t)__cvta_generic_to_shared(p);
}

// ------- tensor-core GEMM: fp16 2-term split (A = Ah+Al fp16, W single fp16)
// -> fp16 z, fused el/er epilogue. Column block == one head (BN = head width).
// RELATIONS LOOPED IN-KERNEL: A smem tile loaded once, B refilled per relation.
template <int K, int BN>
__global__ void __launch_bounds__(256, 2)
gemm_attn_k(const __half* __restrict__ Ahi,
            const __half* __restrict__ Alo,
            const float* __restrict__ W,
            const float* __restrict__ alw,
            const float* __restrict__ arw,
            __half* __restrict__ C,
            float* __restrict__ el, float* __restrict__ er,
            int nrows) {
    constexpr int KP = K + 8;            // fp16 row stride; byte stride mult of 16
    constexpr int M = NH * BN;
    constexpr int JN = BN / 8;
    extern __shared__ __half sm[];
    __half* Ah = sm;                     // [128][KP]
    __half* Al = Ah + 128 * KP;          // [128][KP]
    __half* Bh = Al + 128 * KP;          // [BN][KP]

    const int head = blockIdx.x;
    const int colBase = head * BN;
    const int rowBase = blockIdx.y * 128;
    const int tid = threadIdx.x;

    // ---- A fill (once per CTA; pre-split fp16, plain copies) ----
    constexpr int CPR = K / 8;
    for (int c = tid; c < 128 * CPR; c += 256) {
        int row = c / CPR;
        int cb = c % CPR;
        int grow = rowBase + row;
        uint4 vh = make_uint4(0u, 0u, 0u, 0u), vl = vh;
        if (grow < nrows) {
            vh = *(const uint4*)(Ahi + (size_t)grow * K + cb * 8);
            vl = *(const uint4*)(Alo + (size_t)grow * K + cb * 8);
        }
        *(uint4*)&Ah[row * KP + cb * 8] = vh;
        *(uint4*)&Al[row * KP + cb * 8] = vl;
    }

    const int warp = tid >> 5, lane = tid & 31;
    const int g = lane >> 2, t = lane & 3;
    const int mrow = warp * 16;

    // ldmatrix lane base addresses (bytes, shared space) — loop-invariant
    const int lrow = lane & 7, lq = lane >> 3;
    const int aRow = mrow + lrow + (lq & 1) * 8;
    const int aCol = (lq >> 1) * 8;
    const uint32_t ahBase = smem_u32(Ah) + (uint32_t)(aRow * KP + aCol) * 2u;
    const uint32_t alBase = smem_u32(Al) + (uint32_t)(aRow * KP + aCol) * 2u;
    const int bRow = lrow + (lq >> 1) * 8;
    const int bCol = (lq & 1) * 8;
    const uint32_t bhBase = smem_u32(Bh) + (uint32_t)(bRow * KP + bCol) * 2u;
    const int b2Row = lrow;
    const int b2Col = ((lane >> 3) & 1) * 8;
    const uint32_t bhBase2 = smem_u32(Bh) + (uint32_t)(b2Row * KP + b2Col) * 2u;

    const int row0 = rowBase + mrow + g;

    for (int r = 0; r < RR; r++) {
        // protects A fill (first iter) and previous B readers (later iters)
        __syncthreads();
        const float* Wr = W + (size_t)r * K * M;
        for (int idx = tid; idx < K * BN; idx += 256) {
            int k = idx / BN, n = idx % BN;
            Bh[n * KP + k] = __float2half(Wr[(size_t)k * M + colBase + n]);
        }
        __syncthreads();

        float acc[JN][4];
#pragma unroll
        for (int j = 0; j < JN; j++)
#pragma unroll
            for (int q = 0; q < 4; q++) acc[j][q] = 0.f;

#pragma unroll
        for (int ks = 0; ks < K / 16; ks++) {
            const uint32_t koff = (uint32_t)ks * 32u;   // 16 fp16 = 32 bytes
            uint32_t ah[4], al_[4];
            ldsm4(ah, ahBase + koff);
            ldsm4(al_, alBase + koff);
#pragma unroll
            for (int jp = 0; jp < JN / 2; jp++) {
                const uint32_t joff = (uint32_t)(jp * 16 * KP) * 2u + koff;
                uint32_t bh[4];
                ldsm4(bh, bhBase + joff);
                mma16816h(acc[2 * jp], ah, bh[0], bh[1]);
                mma16816h(acc[2 * jp], al_, bh[0], bh[1]);
                mma16816h(acc[2 * jp + 1], ah, bh[2], bh[3]);
                mma16816h(acc[2 * jp + 1], al_, bh[2], bh[3]);
            }
            if (JN & 1) {
                constexpr int j = JN - 1;
                const uint32_t joff = (uint32_t)(j * 8 * KP) * 2u + koff;
                uint32_t bh[2];
                ldsm2(bh, bhBase2 + joff);
                mma16816h(acc[j], ah, bh[0], bh[1]);
                mma16816h(acc[j], al_, bh[0], bh[1]);
            }
        }

        // store z (fp16)
        __half* Cr = C + (size_t)r * nrows * M;
#pragma unroll
        for (int j = 0; j < JN; j++) {
            int col = colBase + j * 8 + 2 * t;
            if (row0 < nrows) {
                __half2 v = __floats2half2_rn(acc[j][0], acc[j][1]);
                *(__half2*)(Cr + (size_t)row0 * M + col) = v;
            }
            if (row0 + 8 < nrows) {
                __half2 v = __floats2half2_rn(acc[j][2], acc[j][3]);
                *(__half2*)(Cr + (size_t)(row0 + 8) * M + col) = v;
            }
        }

        // fused el/er epilogue
        const float* alr = alw + ((size_t)r * NH + head) * BN;
        const float* arr = arw + ((size_t)r * NH + head) * BN;
        float pel0 = 0.f, pel1 = 0.f, per0 = 0.f, per1 = 0.f;
#pragma unroll
        for (int j = 0; j < JN; j++) {
            int c0 = j * 8 + 2 * t;
            float w0 = alr[c0], w1 = alr[c0 + 1];
            float v0 = arr[c0], v1 = arr[c0 + 1];
            pel0 += acc[j][0] * w0 + acc[j][1] * w1;
            pel1 += acc[j][2] * w0 + acc[j][3] * w1;
            per0 += acc[j][0] * v0 + acc[j][1] * v1;
            per1 += acc[j][2] * v0 + acc[j][3] * v1;
        }
#pragma unroll
        for (int o = 1; o <= 2; o <<= 1) {
            pel0 += __shfl_xor_sync(0xffffffffu, pel0, o);
            pel1 += __shfl_xor_sync(0xffffffffu, pel1, o);
            per0 += __shfl_xor_sync(0xffffffffu, per0, o);
            per1 += __shfl_xor_sync(0xffffffffu, per1, o);
        }
        if (t == 0) {
            if (row0 < nrows) {
                el[((size_t)r * NN + row0) * 4 + head] = pel0;
                er[((size_t)r * NN + row0) * 4 + head] = per0;
            }
            if (row0 + 8 < nrows) {
                el[((size_t)r * NN + row0 + 8) * 4 + head] = pel1;
                er[((size_t)r * NN + row0 + 8) * 4 + head] = per1;
            }
        }
    }
}

// ------- per-(rel,node): SINGLE PASS unnormalized alpha + 1/s ---------------
// m = lrelu(global_max(el) + er[n]) >= true max -> overflow-safe, ratio exact.
__global__ void statsalpha_k(const float* __restrict__ el, const float* __restrict__ er,
                             const int* __restrict__ ptr, const int* __restrict__ csrc,
                             const int* __restrict__ gmax,
                             float4* __restrict__ calpha, float4* __restrict__ inv4) {
    int w = (blockIdx.x * blockDim.x + threadIdx.x) >> 5;
    int lane = threadIdx.x & 31;
    if (w >= RR * NN) return;
    int r = w / NN, n = w % NN;
    int beg = ptr[r * (NN + 1) + n];
    int end = ptr[r * (NN + 1) + n + 1];
    if (beg == end) {
        if (lane == 0) inv4[w] = make_float4(0.f, 0.f, 0.f, 0.f);
        return;
    }
    const float* er4 = er + (size_t)w * 4;
    float er0 = er4[0], er1 = er4[1], er2 = er4[2];
    const float m0 = lrelu(decf(gmax[r * 4 + 0]) + er0);
    const float m1 = lrelu(decf(gmax[r * 4 + 1]) + er1);
    const float m2 = lrelu(decf(gmax[r * 4 + 2]) + er2);
    const int* cs = csrc + (size_t)r * EE;
    const float4* el4 = (const float4*)el + (size_t)r * NN;

    float s0 = 0.f, s1 = 0.f, s2 = 0.f;
    float4* ca = calpha + (size_t)r * EE;
    for (int i = beg + lane; i < end; i += 32) {
        const float4 e4 = el4[cs[i]];
        float a0 = __expf(lrelu(e4.x + er0) - m0);
        float a1 = __expf(lrelu(e4.y + er1) - m1);
        float a2 = __expf(lrelu(e4.z + er2) - m2);
        s0 += a0; s1 += a1; s2 += a2;
        ca[i] = make_float4(a0, a1, a2, 0.f);
    }
#pragma unroll
    for (int o = 16; o; o >>= 1) {
        s0 += __shfl_xor_sync(0xffffffffu, s0, o);
        s1 += __shfl_xor_sync(0xffffffffu, s1, o);
        s2 += __shfl_xor_sync(0xffffffffu, s2, o);
    }
    if (lane == 0)
        inv4[w] = make_float4(s0 > 0.f ? 1.f / s0 : 0.f,
                              s1 > 0.f ? 1.f / s1 : 0.f,
                              s2 > 0.f ? 1.f / s2 : 0.f, 0.f);
}

// ---------------- aggregation: fp16-z weighted gather, scale by 1/s --------
// F16OUT: write fp16 hi/lo (layer-1 hidden). else fp32 out (final).
template <int OUT, bool RELU, bool F16OUT>
__global__ void agg_k(const __half* __restrict__ z, const float4* __restrict__ calpha,
                      const float4* __restrict__ inv4, const float* __restrict__ bias,
                      const int* __restrict__ ptr, const int* __restrict__ csrc,
                      float* __restrict__ outf,
                      __half* __restrict__ ohi, __half* __restrict__ olo) {
    int w = (blockIdx.x * blockDim.x + threadIdx.x) >> 5;
    int lane = threadIdx.x & 31;
    if (w >= NN) return;
    const int n = w;
    constexpr int HC = OUT / 2;
    const bool act = lane < HC;
    float totx = 0.f, toty = 0.f;
    for (int r = 0; r < RR; r++) {
        int beg = ptr[r * (NN + 1) + n];
        int end = ptr[r * (NN + 1) + n + 1];
        const int* cs = csrc + (size_t)r * EE;
        const float4* cal = calpha + (size_t)r * EE;
        const __half2* zr = (const __half2*)(z + (size_t)r * NN * (NH * OUT));
        const float4 inv = inv4[(size_t)r * NN + n];

        float a0x = 0, a0y = 0, a1x = 0, a1y = 0, a2x = 0, a2y = 0;
        int i = beg;
        for (; i + 1 < end; i += 2) {
            int sA = cs[i], sB = cs[i + 1];
            float4 wA = cal[i], wB = cal[i + 1];
            const __half2* zA = zr + (size_t)sA * (NH * HC);
            const __half2* zB = zr + (size_t)sB * (NH * HC);
            if (act) {
                float2 v;
                v = __half22float2(zA[0 * HC + lane]); a0x += wA.x * v.x; a0y += wA.x * v.y;
                v = __half22float2(zB[0 * HC + lane]); a0x += wB.x * v.x; a0y += wB.x * v.y;
                v = __half22float2(zA[1 * HC + lane]); a1x += wA.y * v.x; a1y += wA.y * v.y;
                v = __half22float2(zB[1 * HC + lane]); a1x += wB.y * v.x; a1y += wB.y * v.y;
                v = __half22float2(zA[2 * HC + lane]); a2x += wA.z * v.x; a2y += wA.z * v.y;
                v = __half22float2(zB[2 * HC + lane]); a2x += wB.z * v.x; a2y += wB.z * v.y;
            }
        }
        if (i < end) {
            int sA = cs[i];
            float4 wA = cal[i];
            const __half2* zA = zr + (size_t)sA * (NH * HC);
            if (act) {
                float2 v;
                v = __half22float2(zA[0 * HC + lane]); a0x += wA.x * v.x; a0y += wA.x * v.y;
                v = __half22float2(zA[1 * HC + lane]); a1x += wA.y * v.x; a1y += wA.y * v.y;
                v = __half22float2(zA[2 * HC + lane]); a2x += wA.z * v.x; a2y += wA.z * v.y;
            }
        }
        if (act) {
            const float2* br = (const float2*)(bias + (size_t)r * NH * OUT);
            float2 b0 = br[0 * HC + lane], b1 = br[1 * HC + lane], b2 = br[2 * HC + lane];
            float t0x = a0x * inv.x + b0.x, t0y = a0y * inv.x + b0.y;
            float t1x = a1x * inv.y + b1.x, t1y = a1y * inv.y + b1.y;
            float t2x = a2x * inv.z + b2.x, t2y = a2y * inv.z + b2.y;
            if (RELU) {
                t0x = fmaxf(t0x, 0.f); t0y = fmaxf(t0y, 0.f);
                t1x = fmaxf(t1x, 0.f); t1y = fmaxf(t1y, 0.f);
                t2x = fmaxf(t2x, 0.f); t2y = fmaxf(t2y, 0.f);
            }
            totx += (t0x + t1x + t2x) * (1.f / NH);
            toty += (t0y + t1y + t2y) * (1.f / NH);
        }
    }
    if (!act) return;
    totx *= (1.f / RR);
    toty *= (1.f / RR);
    if (F16OUT) {
        __half hx = __float2half(totx);
        __half hy = __float2half(toty);
        __half2 hv; hv.x = hx; hv.y = hy;
        __half2 lv;
        lv.x = __float2half(totx - __half2float(hx));
        lv.y = __float2half(toty - __half2float(hy));
        ((__half2*)ohi)[(size_t)n * HC + lane] = hv;
        ((__half2*)olo)[(size_t)n * HC + lane] = lv;
    } else {
        *(float2*)(outf + (size_t)n * OUT + 2 * lane) = make_float2(totx, toty);
    }
}

// ---------------- stream/event singletons (host resources, no device mem) --
static cudaStream_t g_s2 = nullptr;
static cudaEvent_t g_evFork = nullptr, g_evJoin = nullptr;
static void ensure_side_stream() {
    if (!g_s2) {
        cudaStreamCreateWithFlags(&g_s2, cudaStreamNonBlocking);
        cudaEventCreateWithFlags(&g_evFork, cudaEventDisableTiming);
        cudaEventCreateWithFlags(&g_evJoin, cudaEventDisableTiming);
    }
}

// ---------------- launch ----------------
extern "C" void kernel_launch(void* const* d_in, const int* in_sizes, int n_in,
                              void* d_out, int out_size) {
    const float* feat = (const float*)d_in[0];
    const int*   src  = (const int*)d_in[1];
    const int*   dst  = (const int*)d_in[2];
    const float* W1   = (const float*)d_in[3];
    const float* al1  = (const float*)d_in[4];
    const float* ar1  = (const float*)d_in[5];
    const float* b1   = (const float*)d_in[6];
    const float* W2   = (const float*)d_in[7];
    const float* al2  = (const float*)d_in[8];
    const float* ar2  = (const float*)d_in[9];
    const float* b2   = (const float*)d_in[10];
    float* out = (float*)d_out;

    ensure_side_stream();

    unsigned char* base = nullptr;
    cudaGetSymbolAddress((void**)&base, g_scratch);

    size_t off = 0;
    auto carve = [&](size_t bytes) -> unsigned char* {
        unsigned char* p = base + off;
        off += (bytes + 255) & ~(size_t)255;
        return p;
    };
    __half* z1 = (__half*)carve((size_t)RR * NN * NH * FHID * 2);
    __half* z2 = (__half*)carve((size_t)RR * NN * NH * FC * 2);
    float* el   = (float*)carve((size_t)RR * NN * 4 * 4);
    float* er   = (float*)carve((size_t)RR * NN * 4 * 4);
    float4* inv4 = (float4*)carve((size_t)RR * NN * 16);
    float4* calpha = (float4*)carve((size_t)RR * EE * 16);
    int* cnt  = (int*)carve((size_t)RR * NN * 4);
    int* ptr  = (int*)carve((size_t)RR * (NN + 1) * 4);
    int* cur  = (int*)carve((size_t)RR * NN * 4);
    int* csrc = (int*)carve((size_t)RR * EE * 4);
    __half* fhi = (__half*)carve((size_t)NN * FIN * 2);
    __half* flo = (__half*)carve((size_t)NN * FIN * 2);
    __half* hhi = (__half*)carve((size_t)NN * FHID * 2);
    __half* hlo = (__half*)carve((size_t)NN * FHID * 2);
    int* gmax = (int*)carve((size_t)2 * RR * 4 * 4);   // [2 layers][RR][4]

    const int SMEM1 = (2 * 128 * (FIN + 8) + 64 * (FIN + 8)) * 2;   // K=128,BN=64 (fp16)
    const int SMEM2 = (2 * 128 * (FHID + 8) + 40 * (FHID + 8)) * 2; // K=64, BN=40
    cudaFuncSetAttribute((const void*)gemm_attn_k<FIN, 64>,
                         cudaFuncAttributeMaxDynamicSharedMemorySize, SMEM1);
    cudaFuncSetAttribute((const void*)gemm_attn_k<FHID, 40>,
                         cudaFuncAttributeMaxDynamicSharedMemorySize, SMEM2);
    cudaFuncSetAttribute((const void*)gemm_attn_k<FIN, 64>,
                         cudaFuncAttributePreferredSharedMemoryCarveout, 100);
    cudaFuncSetAttribute((const void*)gemm_attn_k<FHID, 40>,
                         cudaFuncAttributePreferredSharedMemoryCarveout, 100);

    // ---- fork: gmax init + CSR build on side stream, concurrent with gemm1 --
    cudaEventRecord(g_evFork, 0);
    cudaStreamWaitEvent(g_s2, g_evFork, 0);
    initgmax_k<<<1, 32, 0, g_s2>>>(gmax);
    cudaMemsetAsync(cnt, 0, (size_t)RR * NN * 4, g_s2);
    count_k<<<(RR * EE + 255) / 256, 256, 0, g_s2>>>(dst, cnt);
    scan_k<<<RR, 1024, 0, g_s2>>>(cnt, ptr, cur);
    scatter_k<<<(RR * EE + 255) / 256, 256, 0, g_s2>>>(src, dst, cur, csrc);
    cudaEventRecord(g_evJoin, g_s2);

    // ---- main stream: layer-1 GEMM path ----
    split16_k<<<(NN * FIN / 4 + 255) / 256, 256>>>(feat, fhi, flo, NN * FIN / 4);
    {
        dim3 grid(NH, (NN + 127) / 128);
        gemm_attn_k<FIN, 64><<<grid, 256, SMEM1>>>(fhi, flo, W1, al1, ar1, z1, el, er, NN);
    }

    // ---- join: edge phase needs csrc/ptr AND el/er AND gmax init ----
    cudaStreamWaitEvent(0, g_evJoin, 0);
    {
        dim3 grid((NN + 255) / 256, RR);
        maxel_k<<<grid, 256>>>((const float4*)el, gmax);
    }
    statsalpha_k<<<(RR * NN * 32 + 255) / 256, 256>>>(el, er, ptr, csrc, gmax, calpha, inv4);
    agg_k<FHID, true, true><<<(NN * 32 + 255) / 256, 256>>>(z1, calpha, inv4, b1, ptr, csrc,
                                                            nullptr, hhi, hlo);

    // ---- layer 2 ----
    {
        dim3 grid(NH, (NN + 127) / 128);
        gemm_attn_k<FHID, 40><<<grid, 256, SMEM2>>>(hhi, hlo, W2, al2, ar2, z2, el, er, NN);
    }
    {
        dim3 grid((NN + 255) / 256, RR);
        maxel_k<<<grid, 256>>>((const float4*)el, gmax + RR * 4);
    }
    statsalpha_k<<<(RR * NN * 32 + 255) / 256, 256>>>(el, er, ptr, csrc, gmax + RR * 4,
                                                      calpha, inv4);
    agg_k<FC, false, false><<<(NN * 32 + 255) / 256, 256>>>(z2, calpha, inv4, b2, ptr, csrc,
                                                            out, nullptr, nullptr);

    (void)in_sizes; (void)n_in; (void)out_size;
}

// round 14
// speedup vs baseline: 1.2754x; 1.2754x over previous
#include <cuda_runtime.h>
#include <cuda_bf16.h>
#include <cuda_fp16.h>
#include <math.h>
#include <stdint.h>

// ---------------- problem constants ----------------
#define NN   50000   // nodes
#define EE   400000  // edges per relation
#define RR   3       // relations
#define FIN  128     // input features
#define FHID 64      // hidden features
#define FC   40      // classes
#define NH   3       // heads
#define NEG_SLOPE 0.2f

#define SCRATCH_BYTES (192ull * 1024 * 1024)
__device__ __align__(256) unsigned char g_scratch[SCRATCH_BYTES];

__device__ __forceinline__ float lrelu(float x) { return x > 0.f ? x : NEG_SLOPE * x; }

// ---------------- CSR build ----------------
__global__ void count_k(const int* __restrict__ dst, int* __restrict__ cnt) {
    int i = blockIdx.x * blockDim.x + threadIdx.x;
    if (i >= RR * EE) return;
    int r = i / EE;
    atomicAdd(&cnt[r * NN + dst[i]], 1);
}

__global__ void scan_k(const int* __restrict__ cnt, int* __restrict__ ptr, int* __restrict__ cur) {
    const int r = blockIdx.x;
    const int t = threadIdx.x;
    const int CH = (NN + 1023) / 1024;
    int s0 = t * CH;
    int s1 = s0 + CH; if (s1 > NN) s1 = NN;
    if (s0 > NN) s0 = NN;
    int sum = 0;
    for (int n = s0; n < s1; n++) sum += cnt[r * NN + n];
    __shared__ int sh[1024];
    sh[t] = sum;
    __syncthreads();
    for (int off = 1; off < 1024; off <<= 1) {
        int v = (t >= off) ? sh[t - off] : 0;
        __syncthreads();
        sh[t] += v;
        __syncthreads();
    }
    int base = sh[t] - sum;
    for (int n = s0; n < s1; n++) {
        ptr[r * (NN + 1) + n] = base;
        cur[r * NN + n] = base;
        base += cnt[r * NN + n];
    }
    if (t == 1023) ptr[r * (NN + 1) + NN] = sh[1023];
}

__global__ void scatter_k(const int* __restrict__ src, const int* __restrict__ dst,
                          int* __restrict__ cur, int* __restrict__ csrc) {
    int i = blockIdx.x * blockDim.x + threadIdx.x;
    if (i >= RR * EE) return;
    int r = i / EE;
    int d = dst[i];
    int pos = atomicAdd(&cur[r * NN + d], 1);
    csrc[(size_t)r * EE + pos] = src[i];
}

// ---------------- fp32 -> (fp16 hi, fp16 lo) split, one pass ----------------
__global__ void split16_k(const float* __restrict__ in, __half* __restrict__ hi,
                          __half* __restrict__ lo, int n4) {
    int i = blockIdx.x * blockDim.x + threadIdx.x;
    if (i >= n4) return;
    float4 v = ((const float4*)in)[i];
    __half h0 = __float2half(v.x), h1 = __float2half(v.y);
    __half h2 = __float2half(v.z), h3 = __float2half(v.w);
    __half hv[4] = {h0, h1, h2, h3};
    __half lv[4] = {
        __float2half(v.x - __half2float(h0)),
        __float2half(v.y - __half2float(h1)),
        __float2half(v.z - __half2float(h2)),
        __float2half(v.w - __half2float(h3))};
    ((uint2*)hi)[i] = *(uint2*)hv;
    ((uint2*)lo)[i] = *(uint2*)lv;
}

// ---------------- mma / ldmatrix helpers ----------------
__device__ __forceinline__ void mma16816h(float* c, const uint32_t* a, uint32_t b0, uint32_t b1) {
    asm volatile(
        "mma.sync.aligned.m16n8k16.row.col.f32.f16.f16.f32 "
        "{%0,%1,%2,%3}, {%4,%5,%6,%7}, {%8,%9}, {%0,%1,%2,%3};"
        : "+f"(c[0]), "+f"(c[1]), "+f"(c[2]), "+f"(c[3])
        : "r"(a[0]), "r"(a[1]), "r"(a[2]), "r"(a[3]), "r"(b0), "r"(b1));
}

__device__ __forceinline__ void ldsm4(uint32_t* r, uint32_t addr) {
    asm volatile("ldmatrix.sync.aligned.m8n8.x4.shared.b16 {%0,%1,%2,%3}, [%4];"
                 : "=r"(r[0]), "=r"(r[1]), "=r"(r[2]), "=r"(r[3]) : "r"(addr));
}
__device__ __forceinline__ void ldsm2(uint32_t* r, uint32_t addr) {
    asm volatile("ldmatrix.sync.aligned.m8n8.x2.shared.b16 {%0,%1}, [%2];"
                 : "=r"(r[0]), "=r"(r[1]) : "r"(addr));
}
__device__ __forceinline__ uint32_t smem_u32(const void* p) {
    return (uint32_t)__cvta_generic_to_shared(p);
}

// ------- tensor-core GEMM: fp16 2-term split (A = Ah+Al fp16, W single fp16)
// -> fp16 z, fused el/er epilogue. Column block == one head (BN = head width).
// RELATIONS LOOPED IN-KERNEL: A smem tile loaded once, B refilled per relation.
template <int K, int BN>
__global__ void __launch_bounds__(256, 2)
gemm_attn_k(const __half* __restrict__ Ahi,
            const __half* __restrict__ Alo,
            const float* __restrict__ W,
            const float* __restrict__ alw,
            const float* __restrict__ arw,
            __half* __restrict__ C,
            float* __restrict__ el, float* __restrict__ er,
            int nrows) {
    constexpr int KP = K + 8;            // fp16 row stride; byte stride mult of 16
    constexpr int M = NH * BN;
    constexpr int JN = BN / 8;
    extern __shared__ __half sm[];
    __half* Ah = sm;                     // [128][KP]
    __half* Al = Ah + 128 * KP;          // [128][KP]
    __half* Bh = Al + 128 * KP;          // [BN][KP]

    const int head = blockIdx.x;
    const int colBase = head * BN;
    const int rowBase = blockIdx.y * 128;
    const int tid = threadIdx.x;

    // ---- A fill (once per CTA; pre-split fp16, plain copies) ----
    constexpr int CPR = K / 8;
    for (int c = tid; c < 128 * CPR; c += 256) {
        int row = c / CPR;
        int cb = c % CPR;
        int grow = rowBase + row;
        uint4 vh = make_uint4(0u, 0u, 0u, 0u), vl = vh;
        if (grow < nrows) {
            vh = *(const uint4*)(Ahi + (size_t)grow * K + cb * 8);
            vl = *(const uint4*)(Alo + (size_t)grow * K + cb * 8);
        }
        *(uint4*)&Ah[row * KP + cb * 8] = vh;
        *(uint4*)&Al[row * KP + cb * 8] = vl;
    }

    const int warp = tid >> 5, lane = tid & 31;
    const int g = lane >> 2, t = lane & 3;
    const int mrow = warp * 16;

    // ldmatrix lane base addresses (bytes, shared space) — loop-invariant
    const int lrow = lane & 7, lq = lane >> 3;
    const int aRow = mrow + lrow + (lq & 1) * 8;
    const int aCol = (lq >> 1) * 8;
    const uint32_t ahBase = smem_u32(Ah) + (uint32_t)(aRow * KP + aCol) * 2u;
    const uint32_t alBase = smem_u32(Al) + (uint32_t)(aRow * KP + aCol) * 2u;
    const int bRow = lrow + (lq >> 1) * 8;
    const int bCol = (lq & 1) * 8;
    const uint32_t bhBase = smem_u32(Bh) + (uint32_t)(bRow * KP + bCol) * 2u;
    const int b2Row = lrow;
    const int b2Col = ((lane >> 3) & 1) * 8;
    const uint32_t bhBase2 = smem_u32(Bh) + (uint32_t)(b2Row * KP + b2Col) * 2u;

    const int row0 = rowBase + mrow + g;

    for (int r = 0; r < RR; r++) {
        // protects A fill (first iter) and previous B readers (later iters)
        __syncthreads();
        const float* Wr = W + (size_t)r * K * M;
        for (int idx = tid; idx < K * BN; idx += 256) {
            int k = idx / BN, n = idx % BN;
            Bh[n * KP + k] = __float2half(Wr[(size_t)k * M + colBase + n]);
        }
        __syncthreads();

        float acc[JN][4];
#pragma unroll
        for (int j = 0; j < JN; j++)
#pragma unroll
            for (int q = 0; q < 4; q++) acc[j][q] = 0.f;

#pragma unroll
        for (int ks = 0; ks < K / 16; ks++) {
            const uint32_t koff = (uint32_t)ks * 32u;   // 16 fp16 = 32 bytes
            uint32_t ah[4], al_[4];
            ldsm4(ah, ahBase + koff);
            ldsm4(al_, alBase + koff);
#pragma unroll
            for (int jp = 0; jp < JN / 2; jp++) {
                const uint32_t joff = (uint32_t)(jp * 16 * KP) * 2u + koff;
                uint32_t bh[4];
                ldsm4(bh, bhBase + joff);
                mma16816h(acc[2 * jp], ah, bh[0], bh[1]);
                mma16816h(acc[2 * jp], al_, bh[0], bh[1]);
                mma16816h(acc[2 * jp + 1], ah, bh[2], bh[3]);
                mma16816h(acc[2 * jp + 1], al_, bh[2], bh[3]);
            }
            if (JN & 1) {
                constexpr int j = JN - 1;
                const uint32_t joff = (uint32_t)(j * 8 * KP) * 2u + koff;
                uint32_t bh[2];
                ldsm2(bh, bhBase2 + joff);
                mma16816h(acc[j], ah, bh[0], bh[1]);
                mma16816h(acc[j], al_, bh[0], bh[1]);
            }
        }

        // store z (fp16)
        __half* Cr = C + (size_t)r * nrows * M;
#pragma unroll
        for (int j = 0; j < JN; j++) {
            int col = colBase + j * 8 + 2 * t;
            if (row0 < nrows) {
                __half2 v = __floats2half2_rn(acc[j][0], acc[j][1]);
                *(__half2*)(Cr + (size_t)row0 * M + col) = v;
            }
            if (row0 + 8 < nrows) {
                __half2 v = __floats2half2_rn(acc[j][2], acc[j][3]);
                *(__half2*)(Cr + (size_t)(row0 + 8) * M + col) = v;
            }
        }

        // fused el/er epilogue
        const float* alr = alw + ((size_t)r * NH + head) * BN;
        const float* arr = arw + ((size_t)r * NH + head) * BN;
        float pel0 = 0.f, pel1 = 0.f, per0 = 0.f, per1 = 0.f;
#pragma unroll
        for (int j = 0; j < JN; j++) {
            int c0 = j * 8 + 2 * t;
            float w0 = alr[c0], w1 = alr[c0 + 1];
            float v0 = arr[c0], v1 = arr[c0 + 1];
            pel0 += acc[j][0] * w0 + acc[j][1] * w1;
            pel1 += acc[j][2] * w0 + acc[j][3] * w1;
            per0 += acc[j][0] * v0 + acc[j][1] * v1;
            per1 += acc[j][2] * v0 + acc[j][3] * v1;
        }
#pragma unroll
        for (int o = 1; o <= 2; o <<= 1) {
            pel0 += __shfl_xor_sync(0xffffffffu, pel0, o);
            pel1 += __shfl_xor_sync(0xffffffffu, pel1, o);
            per0 += __shfl_xor_sync(0xffffffffu, per0, o);
            per1 += __shfl_xor_sync(0xffffffffu, per1, o);
        }
        if (t == 0) {
            if (row0 < nrows) {
                el[((size_t)r * NN + row0) * 4 + head] = pel0;
                er[((size_t)r * NN + row0) * 4 + head] = per0;
            }
            if (row0 + 8 < nrows) {
                el[((size_t)r * NN + row0 + 8) * 4 + head] = pel1;
                er[((size_t)r * NN + row0 + 8) * 4 + head] = per1;
            }
        }
    }
}

// ------- per-(rel,node): max pass + unnormalized alpha + 1/s ----------------
__global__ void statsalpha_k(const float* __restrict__ el, const float* __restrict__ er,
                             const int* __restrict__ ptr, const int* __restrict__ csrc,
                             float4* __restrict__ calpha, float4* __restrict__ inv4) {
    int w = (blockIdx.x * blockDim.x + threadIdx.x) >> 5;
    int lane = threadIdx.x & 31;
    if (w >= RR * NN) return;
    int r = w / NN, n = w % NN;
    int beg = ptr[r * (NN + 1) + n];
    int end = ptr[r * (NN + 1) + n + 1];
    if (beg == end) {
        if (lane == 0) inv4[w] = make_float4(0.f, 0.f, 0.f, 0.f);
        return;
    }
    const float* er4 = er + (size_t)w * 4;
    float er0 = er4[0], er1 = er4[1], er2 = er4[2];
    const int* cs = csrc + (size_t)r * EE;
    const float4* el4 = (const float4*)el + (size_t)r * NN;

    float m0 = -1e30f, m1 = -1e30f, m2 = -1e30f;
    float c0 = 0.f, c1 = 0.f, c2 = 0.f;
    {
        int i = beg + lane;
        if (i < end) {
            const float4 e4 = el4[cs[i]];
            c0 = lrelu(e4.x + er0);
            c1 = lrelu(e4.y + er1);
            c2 = lrelu(e4.z + er2);
            m0 = c0; m1 = c1; m2 = c2;
        }
        for (i += 32; i < end; i += 32) {
            const float4 e4 = el4[cs[i]];
            m0 = fmaxf(m0, lrelu(e4.x + er0));
            m1 = fmaxf(m1, lrelu(e4.y + er1));
            m2 = fmaxf(m2, lrelu(e4.z + er2));
        }
    }
#pragma unroll
    for (int o = 16; o; o >>= 1) {
        m0 = fmaxf(m0, __shfl_xor_sync(0xffffffffu, m0, o));
        m1 = fmaxf(m1, __shfl_xor_sync(0xffffffffu, m1, o));
        m2 = fmaxf(m2, __shfl_xor_sync(0xffffffffu, m2, o));
    }
    float s0 = 0.f, s1 = 0.f, s2 = 0.f;
    float4* ca = calpha + (size_t)r * EE;
    {
        int i = beg + lane;
        if (i < end) {
            float a0 = __expf(c0 - m0);
            float a1 = __expf(c1 - m1);
            float a2 = __expf(c2 - m2);
            s0 += a0; s1 += a1; s2 += a2;
            ca[i] = make_float4(a0, a1, a2, 0.f);
        }
        for (i += 32; i < end; i += 32) {
            const float4 e4 = el4[cs[i]];
            float a0 = __expf(lrelu(e4.x + er0) - m0);
            float a1 = __expf(lrelu(e4.y + er1) - m1);
            float a2 = __expf(lrelu(e4.z + er2) - m2);
            s0 += a0; s1 += a1; s2 += a2;
            ca[i] = make_float4(a0, a1, a2, 0.f);
        }
    }
#pragma unroll
    for (int o = 16; o; o >>= 1) {
        s0 += __shfl_xor_sync(0xffffffffu, s0, o);
        s1 += __shfl_xor_sync(0xffffffffu, s1, o);
        s2 += __shfl_xor_sync(0xffffffffu, s2, o);
    }
    if (lane == 0)
        inv4[w] = make_float4(1.f / s0, 1.f / s1, 1.f / s2, 0.f);
}

// ---------------- aggregation: fp16-z weighted gather, scale by 1/s --------
// F16OUT: write fp16 hi/lo (layer-1 hidden). else fp32 out (final).
// Edge loop unrolled x4 for MLP (z gathers are the latency-bound path).
template <int OUT, bool RELU, bool F16OUT>
__global__ void agg_k(const __half* __restrict__ z, const float4* __restrict__ calpha,
                      const float4* __restrict__ inv4, const float* __restrict__ bias,
                      const int* __restrict__ ptr, const int* __restrict__ csrc,
                      float* __restrict__ outf,
                      __half* __restrict__ ohi, __half* __restrict__ olo) {
    int w = (blockIdx.x * blockDim.x + threadIdx.x) >> 5;
    int lane = threadIdx.x & 31;
    if (w >= NN) return;
    const int n = w;
    constexpr int HC = OUT / 2;
    const bool act = lane < HC;
    float totx = 0.f, toty = 0.f;
    for (int r = 0; r < RR; r++) {
        int beg = ptr[r * (NN + 1) + n];
        int end = ptr[r * (NN + 1) + n + 1];
        const int* cs = csrc + (size_t)r * EE;
        const float4* cal = calpha + (size_t)r * EE;
        const __half2* zr = (const __half2*)(z + (size_t)r * NN * (NH * OUT));
        const float4 inv = inv4[(size_t)r * NN + n];

        float a0x = 0, a0y = 0, a1x = 0, a1y = 0, a2x = 0, a2y = 0;
        int i = beg;
        for (; i + 3 < end; i += 4) {
            int sA = cs[i], sB = cs[i + 1], sC = cs[i + 2], sD = cs[i + 3];
            float4 wA = cal[i], wB = cal[i + 1], wC = cal[i + 2], wD = cal[i + 3];
            const __half2* zA = zr + (size_t)sA * (NH * HC);
            const __half2* zB = zr + (size_t)sB * (NH * HC);
            const __half2* zC = zr + (size_t)sC * (NH * HC);
            const __half2* zD = zr + (size_t)sD * (NH * HC);
            if (act) {
                float2 v;
                v = __half22float2(zA[0 * HC + lane]); a0x += wA.x * v.x; a0y += wA.x * v.y;
                v = __half22float2(zB[0 * HC + lane]); a0x += wB.x * v.x; a0y += wB.x * v.y;
                v = __half22float2(zC[0 * HC + lane]); a0x += wC.x * v.x; a0y += wC.x * v.y;
                v = __half22float2(zD[0 * HC + lane]); a0x += wD.x * v.x; a0y += wD.x * v.y;
                v = __half22float2(zA[1 * HC + lane]); a1x += wA.y * v.x; a1y += wA.y * v.y;
                v = __half22float2(zB[1 * HC + lane]); a1x += wB.y * v.x; a1y += wB.y * v.y;
                v = __half22float2(zC[1 * HC + lane]); a1x += wC.y * v.x; a1y += wC.y * v.y;
                v = __half22float2(zD[1 * HC + lane]); a1x += wD.y * v.x; a1y += wD.y * v.y;
                v = __half22float2(zA[2 * HC + lane]); a2x += wA.z * v.x; a2y += wA.z * v.y;
                v = __half22float2(zB[2 * HC + lane]); a2x += wB.z * v.x; a2y += wB.z * v.y;
                v = __half22float2(zC[2 * HC + lane]); a2x += wC.z * v.x; a2y += wC.z * v.y;
                v = __half22float2(zD[2 * HC + lane]); a2x += wD.z * v.x; a2y += wD.z * v.y;
            }
        }
        for (; i < end; i++) {
            int sA = cs[i];
            float4 wA = cal[i];
            const __half2* zA = zr + (size_t)sA * (NH * HC);
            if (act) {
                float2 v;
                v = __half22float2(zA[0 * HC + lane]); a0x += wA.x * v.x; a0y += wA.x * v.y;
                v = __half22float2(zA[1 * HC + lane]); a1x += wA.y * v.x; a1y += wA.y * v.y;
                v = __half22float2(zA[2 * HC + lane]); a2x += wA.z * v.x; a2y += wA.z * v.y;
            }
        }
        if (act) {
            const float2* br = (const float2*)(bias + (size_t)r * NH * OUT);
            float2 b0 = br[0 * HC + lane], b1 = br[1 * HC + lane], b2 = br[2 * HC + lane];
            float t0x = a0x * inv.x + b0.x, t0y = a0y * inv.x + b0.y;
            float t1x = a1x * inv.y + b1.x, t1y = a1y * inv.y + b1.y;
            float t2x = a2x * inv.z + b2.x, t2y = a2y * inv.z + b2.y;
            if (RELU) {
                t0x = fmaxf(t0x, 0.f); t0y = fmaxf(t0y, 0.f);
                t1x = fmaxf(t1x, 0.f); t1y = fmaxf(t1y, 0.f);
                t2x = fmaxf(t2x, 0.f); t2y = fmaxf(t2y, 0.f);
            }
            totx += (t0x + t1x + t2x) * (1.f / NH);
            toty += (t0y + t1y + t2y) * (1.f / NH);
        }
    }
    if (!act) return;
    totx *= (1.f / RR);
    toty *= (1.f / RR);
    if (F16OUT) {
        __half hx = __float2half(totx);
        __half hy = __float2half(toty);
        __half2 hv; hv.x = hx; hv.y = hy;
        __half2 lv;
        lv.x = __float2half(totx - __half2float(hx));
        lv.y = __float2half(toty - __half2float(hy));
        ((__half2*)ohi)[(size_t)n * HC + lane] = hv;
        ((__half2*)olo)[(size_t)n * HC + lane] = lv;
    } else {
        *(float2*)(outf + (size_t)n * OUT + 2 * lane) = make_float2(totx, toty);
    }
}

// ---------------- stream/event singletons (host resources, no device mem) --
static cudaStream_t g_s2 = nullptr;
static cudaEvent_t g_evFork = nullptr, g_evJoin = nullptr;
static void ensure_side_stream() {
    if (!g_s2) {
        cudaStreamCreateWithFlags(&g_s2, cudaStreamNonBlocking);
        cudaEventCreateWithFlags(&g_evFork, cudaEventDisableTiming);
        cudaEventCreateWithFlags(&g_evJoin, cudaEventDisableTiming);
    }
}

// ---------------- launch ----------------
extern "C" void kernel_launch(void* const* d_in, const int* in_sizes, int n_in,
                              void* d_out, int out_size) {
    const float* feat = (const float*)d_in[0];
    const int*   src  = (const int*)d_in[1];
    const int*   dst  = (const int*)d_in[2];
    const float* W1   = (const float*)d_in[3];
    const float* al1  = (const float*)d_in[4];
    const float* ar1  = (const float*)d_in[5];
    const float* b1   = (const float*)d_in[6];
    const float* W2   = (const float*)d_in[7];
    const float* al2  = (const float*)d_in[8];
    const float* ar2  = (const float*)d_in[9];
    const float* b2   = (const float*)d_in[10];
    float* out = (float*)d_out;

    ensure_side_stream();

    unsigned char* base = nullptr;
    cudaGetSymbolAddress((void**)&base, g_scratch);

    size_t off = 0;
    auto carve = [&](size_t bytes) -> unsigned char* {
        unsigned char* p = base + off;
        off += (bytes + 255) & ~(size_t)255;
        return p;
    };
    __half* z1 = (__half*)carve((size_t)RR * NN * NH * FHID * 2);
    __half* z2 = (__half*)carve((size_t)RR * NN * NH * FC * 2);
    float* el   = (float*)carve((size_t)RR * NN * 4 * 4);
    float* er   = (float*)carve((size_t)RR * NN * 4 * 4);
    float4* inv4 = (float4*)carve((size_t)RR * NN * 16);
    float4* calpha = (float4*)carve((size_t)RR * EE * 16);
    int* cnt  = (int*)carve((size_t)RR * NN * 4);
    int* ptr  = (int*)carve((size_t)RR * (NN + 1) * 4);
    int* cur  = (int*)carve((size_t)RR * NN * 4);
    int* csrc = (int*)carve((size_t)RR * EE * 4);
    __half* fhi = (__half*)carve((size_t)NN * FIN * 2);
    __half* flo = (__half*)carve((size_t)NN * FIN * 2);
    __half* hhi = (__half*)carve((size_t)NN * FHID * 2);
    __half* hlo = (__half*)carve((size_t)NN * FHID * 2);

    const int SMEM1 = (2 * 128 * (FIN + 8) + 64 * (FIN + 8)) * 2;   // K=128,BN=64 (fp16)
    const int SMEM2 = (2 * 128 * (FHID + 8) + 40 * (FHID + 8)) * 2; // K=64, BN=40
    cudaFuncSetAttribute((const void*)gemm_attn_k<FIN, 64>,
                         cudaFuncAttributeMaxDynamicSharedMemorySize, SMEM1);
    cudaFuncSetAttribute((const void*)gemm_attn_k<FHID, 40>,
                         cudaFuncAttributeMaxDynamicSharedMemorySize, SMEM2);
    cudaFuncSetAttribute((const void*)gemm_attn_k<FIN, 64>,
                         cudaFuncAttributePreferredSharedMemoryCarveout, 100);
    cudaFuncSetAttribute((const void*)gemm_attn_k<FHID, 40>,
                         cudaFuncAttributePreferredSharedMemoryCarveout, 100);

    // ---- fork: CSR build on side stream, concurrent with split+gemm1 ----
    cudaEventRecord(g_evFork, 0);
    cudaStreamWaitEvent(g_s2, g_evFork, 0);
    cudaMemsetAsync(cnt, 0, (size_t)RR * NN * 4, g_s2);
    count_k<<<(RR * EE + 255) / 256, 256, 0, g_s2>>>(dst, cnt);
    scan_k<<<RR, 1024, 0, g_s2>>>(cnt, ptr, cur);
    scatter_k<<<(RR * EE + 255) / 256, 256, 0, g_s2>>>(src, dst, cur, csrc);
    cudaEventRecord(g_evJoin, g_s2);

    // ---- main stream: layer-1 GEMM path ----
    split16_k<<<(NN * FIN / 4 + 255) / 256, 256>>>(feat, fhi, flo, NN * FIN / 4);
    {
        dim3 grid(NH, (NN + 127) / 128);
        gemm_attn_k<FIN, 64><<<grid, 256, SMEM1>>>(fhi, flo, W1, al1, ar1, z1, el, er, NN);
    }

    // ---- join: edge phase needs csrc/ptr AND el/er ----
    cudaStreamWaitEvent(0, g_evJoin, 0);
    statsalpha_k<<<(RR * NN * 32 + 255) / 256, 256>>>(el, er, ptr, csrc, calpha, inv4);
    agg_k<FHID, true, true><<<(NN * 32 + 255) / 256, 256>>>(z1, calpha, inv4, b1, ptr, csrc,
                                                            nullptr, hhi, hlo);

    // ---- layer 2 ----
    {
        dim3 grid(NH, (NN + 127) / 128);
        gemm_attn_k<FHID, 40><<<grid, 256, SMEM2>>>(hhi, hlo, W2, al2, ar2, z2, el, er, NN);
    }
    statsalpha_k<<<(RR * NN * 32 + 255) / 256, 256>>>(el, er, ptr, csrc, calpha, inv4);
    agg_k<FC, false, false><<<(NN * 32 + 255) / 256, 256>>>(z2, calpha, inv4, b2, ptr, csrc,
                                                            out, nullptr, nullptr);

    (void)in_sizes; (void)n_in; (void)out_size;
}